// round 5
// baseline (speedup 1.0000x reference)
#include <cuda_runtime.h>

// AdderNet 2D (K=3,S=1,P=1): out[n,f,y,x] = -sum_{c,i,j} |W[f,c,i,j] - xpad[n,c,y+i,x+j]|
// x: [8,64,32,32] f32, W: [64,64,3,3] f32, out: [8,64,32,32] f32.
//
// 512 thr/CTA = 128 position-workers (2 rows) x 4 channel-quarters.
// Rolling software pipeline: w[k] reloaded with next stage's value right after
// its last use -> load-to-use distance ~176 issues, single-buffered (48 regs).

#define CIN   64
#define NFILT 64
#define HW    32
#define NIMG  8

#define FG    16
#define RT    8
#define XROWS (RT + 2)
#define XCOLS 34

#define SX_ELEMS (CIN * XROWS * XCOLS)   // 87040 B
#define SW_ELEMS (CIN * 9 * FG)          // 36864 B
#define SMEM_BYTES ((SX_ELEMS + SW_ELEMS) * 4)
#define ABSM 0x7FFFFFFF7FFFFFFFULL

typedef unsigned long long ull;

__global__ __launch_bounds__(512, 1)
void adder2d_kernel(const float* __restrict__ x,
                    const float* __restrict__ W,
                    float* __restrict__ out)
{
    extern __shared__ float smem[];
    float* sX = smem;                        // [c][r 0..9][col 0..33], zero padded
    float* sW = smem + SX_ELEMS;             // [k=c*9+tap][ff], NEGATED weights
    ull*   sR = (ull*)smem;                  // aliases sX after main loop

    const int tid = threadIdx.x;
    const int qtr = tid >> 7;                // channel quarter 0..3
    const int wk  = tid & 127;
    const int yw  = wk >> 5;                 // rows yw and yw+4
    const int col = wk & 31;
    const int fg  = blockIdx.x;
    const int rt  = blockIdx.y;
    const int n   = blockIdx.z;
    const int y0  = rt * RT;
    const int f0  = fg * FG;

    // ---- load padded x slab ----
    const float* xn = x + (size_t)n * (CIN * HW * HW);
    for (int idx = tid; idx < SX_ELEMS; idx += 512) {
        int c   = idx / (XROWS * XCOLS);
        int rem = idx - c * (XROWS * XCOLS);
        int r   = rem / XCOLS;
        int cc  = rem - r * XCOLS;
        int gr  = y0 - 1 + r;
        int gc  = cc - 1;
        float v = 0.0f;
        if ((unsigned)gr < HW && (unsigned)gc < HW)
            v = xn[(c * HW + gr) * HW + gc];
        sX[idx] = v;
    }
    // ---- NEGATED weights: sW[k*FG + ff] = -W[(f0+ff)*576 + k] ----
    for (int idx = tid; idx < SW_ELEMS; idx += 512) {
        int ff = idx / (CIN * 9);
        int k  = idx - ff * (CIN * 9);
        sW[k * FG + ff] = -W[(f0 + ff) * (CIN * 9) + k];
    }
    __syncthreads();

    ull acc[16];
#pragma unroll
    for (int p = 0; p < 16; p++) acc[p] = 0ULL;

    const int cbeg = qtr * (CIN / 4);
    // stage s = 0..47 : c = cbeg + s/3, i = s%3
    const float* wp = sW + cbeg * 9 * FG;                 // advances +3*FG per stage
    const float* xp = sX + cbeg * (XROWS * XCOLS) + yw * XCOLS + col;

    // ---- prologue: stage-0 loads ----
    ulonglong2 w[12];                         // k = q*3 + j  ->  offset j*FG + q*4
#pragma unroll
    for (int k = 0; k < 12; k++)
        w[k] = *(const ulonglong2*)(wp + (k % 3) * FG + (k / 3) * 4);
    float fc[6];
#pragma unroll
    for (int j = 0; j < 3; j++) { fc[j] = xp[j]; fc[3 + j] = xp[4 * XCOLS + j]; }

#pragma unroll 1
    for (int s = 0; s < 48; s++) {
        const int last = (s == 47);
        // next-stage pointers (harmless dummy reload on last stage)
        const float* wpn = last ? wp : (wp + 3 * FG);
        const float* xpn = last ? xp
                         : (xp + (((s % 3) == 2) ? (XROWS * XCOLS - 2 * XCOLS) : XCOLS));

        // pack current x (lo==hi pairs)
        ull xa[3], xb[3];
#pragma unroll
        for (int j = 0; j < 3; j++) {
            asm("mov.b64 %0, {%1, %1};" : "=l"(xa[j]) : "r"(__float_as_uint(fc[j])));
            asm("mov.b64 %0, {%1, %1};" : "=l"(xb[j]) : "r"(__float_as_uint(fc[3 + j])));
        }
        // prefetch next-stage x early (distance ~ whole stage)
        float fn0 = xpn[0], fn1 = xpn[1], fn2 = xpn[2];
        float fn3 = xpn[4 * XCOLS + 0], fn4 = xpn[4 * XCOLS + 1], fn5 = xpn[4 * XCOLS + 2];

        // core: 12 k-blocks; reload w[k] right after its use (rolling buffer)
#pragma unroll
        for (int k = 0; k < 12; k++) {
            const int q = k / 3, j = k % 3;
            const ulonglong2 wv = w[k];
            ull d;
            asm("add.rn.f32x2 %0, %1, %2;" : "=l"(d) : "l"(xa[j]), "l"(wv.x));
            d &= ABSM;
            asm("add.rn.f32x2 %0, %0, %1;" : "+l"(acc[2 * q]) : "l"(d));
            asm("add.rn.f32x2 %0, %1, %2;" : "=l"(d) : "l"(xa[j]), "l"(wv.y));
            d &= ABSM;
            asm("add.rn.f32x2 %0, %0, %1;" : "+l"(acc[2 * q + 1]) : "l"(d));
            asm("add.rn.f32x2 %0, %1, %2;" : "=l"(d) : "l"(xb[j]), "l"(wv.x));
            d &= ABSM;
            asm("add.rn.f32x2 %0, %0, %1;" : "+l"(acc[8 + 2 * q]) : "l"(d));
            asm("add.rn.f32x2 %0, %1, %2;" : "=l"(d) : "l"(xb[j]), "l"(wv.y));
            d &= ABSM;
            asm("add.rn.f32x2 %0, %0, %1;" : "+l"(acc[8 + 2 * q + 1]) : "l"(d));
            // rolling prefetch: next stage's w for this k-slot
            w[k] = *(const ulonglong2*)(wpn + j * FG + q * 4);
        }

        fc[0] = fn0; fc[1] = fn1; fc[2] = fn2; fc[3] = fn3; fc[4] = fn4; fc[5] = fn5;
        wp = wpn;
        xp = xpn;
    }

    // ---- combine 4 channel quarters (sR aliases sX, now dead) ----
    __syncthreads();
    if (qtr != 0) {
        ull* buf = sR + (size_t)(qtr - 1) * (16 * 128);
#pragma unroll
        for (int p = 0; p < 16; p++) buf[p * 128 + wk] = acc[p];
    }
    __syncthreads();

    if (qtr == 0) {
#pragma unroll
        for (int p = 0; p < 16; p++) {
            ull s = acc[p];
#pragma unroll
            for (int r = 0; r < 3; r++) {
                ull o = sR[(size_t)r * (16 * 128) + p * 128 + wk];
                asm("add.rn.f32x2 %0, %0, %1;" : "+l"(s) : "l"(o));
            }
            acc[p] = s;
        }
#pragma unroll
        for (int pos = 0; pos < 2; pos++) {
            int gy = y0 + yw + pos * 4;
            float* outp = out + (((size_t)n * NFILT + f0) * HW + gy) * HW + col;
#pragma unroll
            for (int pp = 0; pp < 8; pp++) {
                ull s = acc[pos * 8 + pp];
                float lo = __uint_as_float((unsigned)(s & 0xFFFFFFFFULL));
                float hi = __uint_as_float((unsigned)(s >> 32));
                outp[(2 * pp)     * (HW * HW)] = -lo;
                outp[(2 * pp + 1) * (HW * HW)] = -hi;
            }
        }
    }
}

extern "C" void kernel_launch(void* const* d_in, const int* in_sizes, int n_in,
                              void* d_out, int out_size)
{
    const float* x = (const float*)d_in[0];
    const float* W = (const float*)d_in[1];
    if (n_in >= 2 && in_sizes[0] == NFILT * CIN * 9 && in_sizes[1] == NIMG * CIN * HW * HW) {
        const float* t = x; x = W; W = t;
    }
    float* out = (float*)d_out;

    static int smem_set = -1;
    if (smem_set < 0) {
        cudaFuncSetAttribute(adder2d_kernel,
                             cudaFuncAttributeMaxDynamicSharedMemorySize, SMEM_BYTES);
        smem_set = 1;
    }

    dim3 grid(NFILT / FG, HW / RT, NIMG);   // 128 CTAs
    adder2d_kernel<<<grid, 512, SMEM_BYTES>>>(x, W, out);
}

// round 6
// speedup vs baseline: 1.2319x; 1.2319x over previous
#include <cuda_runtime.h>
#include <cuda_fp16.h>

// AdderNet 2D (K=3,S=1,P=1): out[n,f,y,x] = -sum_{c,i,j} |W[f,c,i,j] - xpad[n,c,y+i,x+j]|
// x: [8,64,32,32] f32, W: [64,64,3,3] f32, out: [8,64,32,32] f32.
//
// fp16 core: inputs+negated weights quantized to fp16 in smem; HADD2 diff +
// HADD2 |.| accumulate (rt_SMSP=2, 2 lanes/instr). fp16 partials are promoted
// to fp32 every channel (9 taps, sum <~15) to bound rounding error.
// 512 thr/CTA = 128 position-workers (2 rows) x 4 channel-quarters.

#define CIN   64
#define NFILT 64
#define HW    32
#define NIMG  8

#define FG    16
#define RT    8
#define XROWS (RT + 2)
#define XCOLS 34

#define SX_ELEMS (CIN * XROWS * XCOLS)       // 21760 halves = 43520 B
#define SW_ELEMS (CIN * 9 * FG)              // 9216 halves  = 18432 B
#define SMEM_BYTES ((SX_ELEMS + SW_ELEMS) * 2)   // 61952 B ; reduction aliases (49152 B)

__global__ __launch_bounds__(512, 1)
void adder2d_kernel(const float* __restrict__ x,
                    const float* __restrict__ W,
                    float* __restrict__ out)
{
    extern __shared__ __half smemh[];
    __half* sX = smemh;                       // [c][r 0..9][col 0..33] fp16, zero pad
    __half* sW = smemh + SX_ELEMS;            // [k=c*9+tap][ff 0..15]  fp16, NEGATED
    float*  sR = (float*)smemh;               // aliases after main loop: [3][32][128]

    const int tid = threadIdx.x;
    const int qtr = tid >> 7;                 // channel quarter 0..3
    const int wk  = tid & 127;
    const int yw  = wk >> 5;                  // rows yw and yw+4
    const int col = wk & 31;
    const int fg  = blockIdx.x;
    const int rt  = blockIdx.y;
    const int n   = blockIdx.z;
    const int y0  = rt * RT;
    const int f0  = fg * FG;

    // ---- load padded x slab, fp32 -> fp16 ----
    const float* xn = x + (size_t)n * (CIN * HW * HW);
    for (int idx = tid; idx < SX_ELEMS; idx += 512) {
        int c   = idx / (XROWS * XCOLS);
        int rem = idx - c * (XROWS * XCOLS);
        int r   = rem / XCOLS;
        int cc  = rem - r * XCOLS;
        int gr  = y0 - 1 + r;
        int gc  = cc - 1;
        float v = 0.0f;
        if ((unsigned)gr < HW && (unsigned)gc < HW)
            v = xn[(c * HW + gr) * HW + gc];
        sX[idx] = __float2half_rn(v);
    }
    // ---- NEGATED fp16 weights: sW[k*16 + ff] = -W[(f0+ff)*576 + k] ----
    for (int idx = tid; idx < SW_ELEMS; idx += 512) {
        int ff = idx / (CIN * 9);
        int k  = idx - ff * (CIN * 9);
        sW[k * FG + ff] = __float2half_rn(-W[(f0 + ff) * (CIN * 9) + k]);
    }
    __syncthreads();

    float facc[32];                            // [t 0..15][lane 0..1]
#pragma unroll
    for (int p = 0; p < 32; p++) facc[p] = 0.0f;

    const int cbeg = qtr * (CIN / 4);
    const __half* xrow = sX + cbeg * (XROWS * XCOLS) + yw * XCOLS + col;
    const __half* wch  = sW + cbeg * 9 * FG;

#pragma unroll 1
    for (int c = 0; c < CIN / 4; c++) {
        __half2 hacc[16];
#pragma unroll
        for (int t = 0; t < 16; t++) hacc[t] = __float2half2_rn(0.0f);

#pragma unroll
        for (int i = 0; i < 3; i++) {
            __half2 xa[3], xb[3];
#pragma unroll
            for (int j = 0; j < 3; j++) {
                xa[j] = __half2half2(xrow[i * XCOLS + j]);
                xb[j] = __half2half2(xrow[(i + 4) * XCOLS + j]);
            }
#pragma unroll
            for (int j = 0; j < 3; j++) {
                const uint4 rA = *(const uint4*)(wch + (i * 3 + j) * FG);     // filters 0..7
                const uint4 rB = *(const uint4*)(wch + (i * 3 + j) * FG + 8); // filters 8..15
                const __half2* wa = (const __half2*)&rA;
                const __half2* wb = (const __half2*)&rB;
#pragma unroll
                for (int q = 0; q < 4; q++) {
                    __half2 d;
                    d = __hadd2(xa[j], wa[q]); hacc[q]      = __hadd2(hacc[q],      __habs2(d));
                    d = __hadd2(xa[j], wb[q]); hacc[4 + q]  = __hadd2(hacc[4 + q],  __habs2(d));
                    d = __hadd2(xb[j], wa[q]); hacc[8 + q]  = __hadd2(hacc[8 + q],  __habs2(d));
                    d = __hadd2(xb[j], wb[q]); hacc[12 + q] = __hadd2(hacc[12 + q], __habs2(d));
                }
            }
        }
        // ---- promote this channel's fp16 partials into fp32 accumulators ----
#pragma unroll
        for (int t = 0; t < 16; t++) {
            float2 f = __half22float2(hacc[t]);
            facc[2 * t]     += f.x;
            facc[2 * t + 1] += f.y;
        }
        xrow += XROWS * XCOLS;
        wch  += 9 * FG;
    }

    // ---- combine 4 channel quarters (sR aliases smem, now dead) ----
    __syncthreads();
    if (qtr != 0) {
        float* buf = sR + (size_t)(qtr - 1) * (32 * 128);
#pragma unroll
        for (int p = 0; p < 32; p++) buf[p * 128 + wk] = facc[p];  // conflict-free
    }
    __syncthreads();

    if (qtr == 0) {
#pragma unroll
        for (int p = 0; p < 32; p++) {
            float s = facc[p];
#pragma unroll
            for (int r = 0; r < 3; r++)
                s += sR[(size_t)r * (32 * 128) + p * 128 + wk];
            facc[p] = s;
        }
        // ---- write: t = pos*8 + g*4 + q ; filter = g*8 + 2q + lane ----
#pragma unroll
        for (int t = 0; t < 16; t++) {
            int pos = t >> 3;
            int g   = (t >> 2) & 1;
            int q   = t & 3;
            int f   = g * 8 + q * 2;
            int gy  = y0 + yw + pos * 4;
            float* outp = out + (((size_t)n * NFILT + f0 + f) * HW + gy) * HW + col;
            outp[0]       = -facc[2 * t];
            outp[HW * HW] = -facc[2 * t + 1];
        }
    }
}

extern "C" void kernel_launch(void* const* d_in, const int* in_sizes, int n_in,
                              void* d_out, int out_size)
{
    const float* x = (const float*)d_in[0];
    const float* W = (const float*)d_in[1];
    if (n_in >= 2 && in_sizes[0] == NFILT * CIN * 9 && in_sizes[1] == NIMG * CIN * HW * HW) {
        const float* t = x; x = W; W = t;
    }
    float* out = (float*)d_out;

    static int smem_set = -1;
    if (smem_set < 0) {
        cudaFuncSetAttribute(adder2d_kernel,
                             cudaFuncAttributeMaxDynamicSharedMemorySize, SMEM_BYTES);
        smem_set = 1;
    }

    dim3 grid(NFILT / FG, HW / RT, NIMG);   // 128 CTAs
    adder2d_kernel<<<grid, 512, SMEM_BYTES>>>(x, W, out);
}

// round 7
// speedup vs baseline: 1.3090x; 1.0626x over previous
#include <cuda_runtime.h>
#include <cuda_fp16.h>

// AdderNet 2D (K=3,S=1,P=1): out[n,f,y,x] = -sum_{c,i,j} |W[f,c,i,j] - xpad[n,c,y+i,x+j]|
// x: [8,64,32,32] f32, W: [64,64,3,3] f32, out: [8,64,32,32] f32.
//
// fp16 HADD2 core (abs folds into HADD2 src modifier). 256 CTAs (RT=4),
// 512 thr/CTA, __launch_bounds__(512,2) -> 2 CTAs/SM = 8 warps/SMSP.
// 4-way channel split per CTA; fp16 partials promoted to fp32 every 2 channels.

#define CIN   64
#define NFILT 64
#define HW    32
#define NIMG  8

#define FG    16
#define RT    4
#define XROWS (RT + 2)          // 6
#define XCOLS 34

#define SX_ELEMS (CIN * XROWS * XCOLS)   // 13056 halves = 26112 B
#define SW_ELEMS (CIN * 9 * FG)          // 9216 halves  = 18432 B
#define SMEM_BYTES ((SX_ELEMS + SW_ELEMS) * 2)   // 44544 B ; sR (24KB) aliases sX

__global__ __launch_bounds__(512, 2)
void adder2d_kernel(const float* __restrict__ x,
                    const float* __restrict__ W,
                    float* __restrict__ out)
{
    extern __shared__ __half smemh[];
    __half* sX = smemh;                       // [c][r 0..5][col 0..33] fp16, zero pad
    __half* sW = smemh + SX_ELEMS;            // [k=c*9+tap][ff 0..15]  fp16, NEGATED
    float*  sR = (float*)smemh;               // aliases after main loop: [3][16][128]

    const int tid = threadIdx.x;
    const int qtr = tid >> 7;                 // channel quarter 0..3
    const int wk  = tid & 127;                // worker = one output position
    const int yw  = wk >> 5;                  // 0..3
    const int col = wk & 31;
    const int fg  = blockIdx.x;               // 0..3
    const int rt  = blockIdx.y;               // 0..7
    const int n   = blockIdx.z;               // 0..7
    const int y0  = rt * RT;
    const int f0  = fg * FG;

    // ---- load padded x slab, fp32 -> fp16 ----
    const float* xn = x + (size_t)n * (CIN * HW * HW);
    for (int idx = tid; idx < SX_ELEMS; idx += 512) {
        int c   = idx / (XROWS * XCOLS);
        int rem = idx - c * (XROWS * XCOLS);
        int r   = rem / XCOLS;
        int cc  = rem - r * XCOLS;
        int gr  = y0 - 1 + r;
        int gc  = cc - 1;
        float v = 0.0f;
        if ((unsigned)gr < HW && (unsigned)gc < HW)
            v = xn[(c * HW + gr) * HW + gc];
        sX[idx] = __float2half_rn(v);
    }
    // ---- NEGATED fp16 weights: sW[k*16 + ff] = -W[(f0+ff)*576 + k] ----
    for (int idx = tid; idx < SW_ELEMS; idx += 512) {
        int ff = idx / (CIN * 9);
        int k  = idx - ff * (CIN * 9);
        sW[k * FG + ff] = __float2half_rn(-W[(f0 + ff) * (CIN * 9) + k]);
    }
    __syncthreads();

    float facc[16];
#pragma unroll
    for (int p = 0; p < 16; p++) facc[p] = 0.0f;

    const int cbeg = qtr * (CIN / 4);
    const __half* xrow = sX + cbeg * (XROWS * XCOLS) + yw * XCOLS + col;
    const __half* wch  = sW + cbeg * 9 * FG;

#pragma unroll 1
    for (int cp = 0; cp < CIN / 8; cp++) {     // 8 pairs of channels
        __half2 hacc[8];
#pragma unroll
        for (int t = 0; t < 8; t++) hacc[t] = __float2half2_rn(0.0f);

#pragma unroll
        for (int cc = 0; cc < 2; cc++) {       // 2 channels per promote
#pragma unroll
            for (int i = 0; i < 3; i++) {
                __half2 xa[3];
#pragma unroll
                for (int j = 0; j < 3; j++)
                    xa[j] = __half2half2(xrow[i * XCOLS + j]);
#pragma unroll
                for (int j = 0; j < 3; j++) {
                    const uint4 rA = *(const uint4*)(wch + (i * 3 + j) * FG);     // f 0..7
                    const uint4 rB = *(const uint4*)(wch + (i * 3 + j) * FG + 8); // f 8..15
                    const __half2* wa = (const __half2*)&rA;
                    const __half2* wb = (const __half2*)&rB;
#pragma unroll
                    for (int q = 0; q < 4; q++) {
                        __half2 d;
                        d = __hadd2(xa[j], wa[q]); hacc[q]     = __hadd2(hacc[q],     __habs2(d));
                        d = __hadd2(xa[j], wb[q]); hacc[4 + q] = __hadd2(hacc[4 + q], __habs2(d));
                    }
                }
            }
            xrow += XROWS * XCOLS;
            wch  += 9 * FG;
        }
        // ---- promote fp16 partials (18 taps) into fp32 ----
#pragma unroll
        for (int t = 0; t < 8; t++) {
            float2 f = __half22float2(hacc[t]);
            facc[2 * t]     += f.x;
            facc[2 * t + 1] += f.y;
        }
    }

    // ---- combine 4 channel quarters (sR aliases sX, now dead) ----
    __syncthreads();
    if (qtr != 0) {
        float* buf = sR + (size_t)(qtr - 1) * (16 * 128);
#pragma unroll
        for (int p = 0; p < 16; p++) buf[p * 128 + wk] = facc[p];  // conflict-free
    }
    __syncthreads();

    if (qtr == 0) {
#pragma unroll
        for (int p = 0; p < 16; p++) {
            float s = facc[p];
#pragma unroll
            for (int r = 0; r < 3; r++)
                s += sR[(size_t)r * (16 * 128) + p * 128 + wk];
            facc[p] = s;
        }
        // ---- write: t = g*4 + q ; filter = g*8 + 2q + lane ----
        const int gy = y0 + yw;
#pragma unroll
        for (int t = 0; t < 8; t++) {
            int g = t >> 2;
            int q = t & 3;
            int f = g * 8 + q * 2;
            float* outp = out + (((size_t)n * NFILT + f0 + f) * HW + gy) * HW + col;
            outp[0]       = -facc[2 * t];
            outp[HW * HW] = -facc[2 * t + 1];
        }
    }
}

extern "C" void kernel_launch(void* const* d_in, const int* in_sizes, int n_in,
                              void* d_out, int out_size)
{
    const float* x = (const float*)d_in[0];
    const float* W = (const float*)d_in[1];
    if (n_in >= 2 && in_sizes[0] == NFILT * CIN * 9 && in_sizes[1] == NIMG * CIN * HW * HW) {
        const float* t = x; x = W; W = t;
    }
    float* out = (float*)d_out;

    dim3 grid(NFILT / FG, HW / RT, NIMG);   // 4 x 8 x 8 = 256 CTAs, 2 per SM
    adder2d_kernel<<<grid, 512, SMEM_BYTES>>>(x, W, out);
}